// round 6
// baseline (speedup 1.0000x reference)
#include <cuda_runtime.h>

#define OSC 2048
#define MH  4096
#define NTHR 256

#define XM_P  4104
#define XK_P  4100
#define XF_P  2052
#define XH_P  4100

// ---------------- scratch (no allocs allowed) ----------------
__device__ __align__(16) float g_xm [4 * XM_P];
__device__ __align__(16) float g_xk1[4 * XK_P], g_xk2[4 * XK_P];
__device__ __align__(16) float g_xf1[4 * XF_P], g_xf2[4 * XF_P];
__device__ __align__(16) float g_xh1[4 * XH_P], g_xh2[4 * XH_P];
__device__ __align__(16) float g_mnew[MH];
__device__ __align__(16) float g_h1new[OSC], g_h2new[OSC];
__device__ __align__(16) float g_k1new[OSC], g_k2new[OSC];
__device__ __align__(16) float g_f1new[OSC], g_f2new[OSC];
__device__ unsigned g_cnt_m, g_cnt_done;

__device__ __forceinline__ float sigm(float v) { return 1.0f / (1.0f + __expf(-v)); }
__device__ __forceinline__ int cls_off(int h) { return (4 - h) & 3; }

__device__ __forceinline__ float4 ldw(const float* p) {
    return __ldcs(reinterpret_cast<const float4*>(p));
}
__device__ __forceinline__ float4 ldx(const float* p) {
    return *reinterpret_cast<const float4*>(p);
}
__device__ __forceinline__ float4 ldcg4(const float* p) {
    return __ldcg(reinterpret_cast<const float4*>(p));
}
__device__ __forceinline__ float dot4(float4 a, float4 b) {
    return a.x * b.x + a.y * b.y + a.z * b.z + a.w * b.w;
}
__device__ __forceinline__ unsigned ld_acq(const unsigned* p) {
    unsigned v;
    asm volatile("ld.acquire.gpu.u32 %0, [%1];" : "=r"(v) : "l"(p) : "memory");
    return v;
}
__device__ __forceinline__ void wait_ge(const unsigned* c, unsigned tgt) {
    if (threadIdx.x == 0) {
        while (ld_acq(c) < tgt) __nanosleep(64);
    }
    __syncthreads();
}
__device__ __forceinline__ void signal(unsigned* c) {
    __threadfence();
    atomicAdd(c, 1u);
}

template <int NS>
__device__ __forceinline__ void blockReduce(float (&acc)[NS], float (&out)[NS]) {
    __shared__ float sm[NS][NTHR / 32];
    const int lane = threadIdx.x & 31;
    const int wid  = threadIdx.x >> 5;
#pragma unroll
    for (int s = 0; s < NS; s++) {
        float v = acc[s];
        v += __shfl_down_sync(0xffffffffu, v, 16);
        v += __shfl_down_sync(0xffffffffu, v, 8);
        v += __shfl_down_sync(0xffffffffu, v, 4);
        v += __shfl_down_sync(0xffffffffu, v, 2);
        v += __shfl_down_sync(0xffffffffu, v, 1);
        if (lane == 0) sm[s][wid] = v;
    }
    __syncthreads();
    if (threadIdx.x == 0) {
#pragma unroll
        for (int s = 0; s < NS; s++) {
            float v = 0.0f;
#pragma unroll
            for (int w = 0; w < NTHR / 32; w++) v += sm[s][w];
            out[s] = v;
        }
    }
}

// -------- single-stream GRU unit (m cell) --------
__device__ __forceinline__ void gru_unit_single(
    const float* __restrict__ wih, const float* __restrict__ whh,
    const float* __restrict__ bih, const float* __restrict__ bhh,
    const float* __restrict__ xbufs, int pad, int D,
    const float* __restrict__ hprev, int H, int j,
    float* __restrict__ newout, unsigned* done_cnt)
{
    float acc[6] = {0, 0, 0, 0, 0, 0};
    const int head = (4 - (j & 3)) & 3;
    const float* xc = xbufs + head * pad + cls_off(head);
    const float* wr = wih + (size_t)j * D;
    const float* wz = wih + (size_t)(H + j) * D;
    const float* wn = wih + (size_t)(2 * H + j) * D;
    const int nvec = (D - head) >> 2;
    const int tail = D - head - (nvec << 2);

    if (threadIdx.x < (unsigned)head) {
        int d = threadIdx.x;
        float xv = xc[d];
        acc[0] += wr[d] * xv; acc[1] += wz[d] * xv; acc[2] += wn[d] * xv;
    }
    int c = threadIdx.x;
    for (; c + NTHR < nvec; c += 2 * NTHR) {
        int d0 = head + (c << 2);
        int d1 = d0 + (NTHR << 2);
        float4 a0 = ldw(wr + d0), b0 = ldw(wz + d0), e0 = ldw(wn + d0);
        float4 a1 = ldw(wr + d1), b1 = ldw(wz + d1), e1 = ldw(wn + d1);
        float4 x0 = ldx(xc + d0), x1 = ldx(xc + d1);
        acc[0] += dot4(a0, x0); acc[1] += dot4(b0, x0); acc[2] += dot4(e0, x0);
        acc[0] += dot4(a1, x1); acc[1] += dot4(b1, x1); acc[2] += dot4(e1, x1);
    }
    if (c < nvec) {
        int d0 = head + (c << 2);
        float4 a0 = ldw(wr + d0), b0 = ldw(wz + d0), e0 = ldw(wn + d0);
        float4 x0 = ldx(xc + d0);
        acc[0] += dot4(a0, x0); acc[1] += dot4(b0, x0); acc[2] += dot4(e0, x0);
    }
    if (threadIdx.x < (unsigned)tail) {
        int d = head + (nvec << 2) + threadIdx.x;
        float xv = xc[d];
        acc[0] += wr[d] * xv; acc[1] += wz[d] * xv; acc[2] += wn[d] * xv;
    }

    const float* ur = whh + (size_t)j * H;
    const float* uz = whh + (size_t)(H + j) * H;
    const float* un = whh + (size_t)(2 * H + j) * H;
    const int nvh = H >> 2;
    c = threadIdx.x;
    for (; c + NTHR < nvh; c += 2 * NTHR) {
        int d0 = c << 2, d1 = d0 + (NTHR << 2);
        float4 a0 = ldw(ur + d0), b0 = ldw(uz + d0), e0 = ldw(un + d0);
        float4 a1 = ldw(ur + d1), b1 = ldw(uz + d1), e1 = ldw(un + d1);
        float4 h0 = ldx(hprev + d0), h1v = ldx(hprev + d1);
        acc[3] += dot4(a0, h0); acc[4] += dot4(b0, h0); acc[5] += dot4(e0, h0);
        acc[3] += dot4(a1, h1v); acc[4] += dot4(b1, h1v); acc[5] += dot4(e1, h1v);
    }
    if (c < nvh) {
        int d0 = c << 2;
        float4 a0 = ldw(ur + d0), b0 = ldw(uz + d0), e0 = ldw(un + d0);
        float4 h0 = ldx(hprev + d0);
        acc[3] += dot4(a0, h0); acc[4] += dot4(b0, h0); acc[5] += dot4(e0, h0);
    }

    float s[6];
    blockReduce<6>(acc, s);
    if (threadIdx.x == 0) {
        float r = sigm(s[0] + bih[j] + s[3] + bhh[j]);
        float z = sigm(s[1] + bih[H + j] + s[4] + bhh[H + j]);
        float n = tanhf(s[2] + bih[2 * H + j] + r * (s[5] + bhh[2 * H + j]));
        newout[j] = (1.0f - z) * n + z * hprev[j];
        signal(done_cnt);
    }
}

// -------- G=4 batched dual-stream GRU: one block computes 4 units of same class --------
// smem-staged x vectors kill the per-unit L2 traffic (LTS relief).
__device__ __forceinline__ void dual4(
    const float* __restrict__ wih, const float* __restrict__ whh,
    const float* __restrict__ bih, const float* __restrict__ bhh,
    const float* __restrict__ x1base, const float* __restrict__ x2base,
    int pad, int D,
    const float* __restrict__ h1g, const float* __restrict__ h2g,
    float* __restrict__ out1, float* __restrict__ out2,
    float* sx1, float* sx2, int bi)
{
    const int tid = threadIdx.x;
    const int cc = bi & 3;              // class: j mod 4
    const int t  = bi >> 2;             // 0..127
    const int hc = (4 - cc) & 3;        // head count for this class (D % 4 == 1)

    // stage the class-cc shifted copies of x1/x2 into shared memory
    {
        const float4* gx1 = reinterpret_cast<const float4*>(x1base + hc * pad);
        const float4* gx2 = reinterpret_cast<const float4*>(x2base + hc * pad);
        float4* s1 = reinterpret_cast<float4*>(sx1);
        float4* s2 = reinterpret_cast<float4*>(sx2);
        for (int i = tid; i < (pad >> 2); i += NTHR) { s1[i] = gx1[i]; s2[i] = gx2[i]; }
    }
    __syncthreads();
    const float* x1c = sx1 + cc;   // x1c[i] == xcat1[i]; &x1c[hc] is 16B-aligned
    const float* x2c = sx2 + cc;
    const int nvec = (D - hc) >> 2;
    const int tail = D - hc - (nvec << 2);

#pragma unroll 1
    for (int g = 0; g < 4; g++) {
        const int j = cc + (t << 2) + (g << 9);     // class-preserving unit index
        const float* wr = wih + (size_t)j * D;
        const float* wz = wr + (size_t)OSC * D;
        const float* wn = wz + (size_t)OSC * D;
        float acc[12] = {0, 0, 0, 0, 0, 0, 0, 0, 0, 0, 0, 0};

        if (tid < hc) {
            float a = x1c[tid], b = x2c[tid];
            float w0 = wr[tid], w1 = wz[tid], w2 = wn[tid];
            acc[0] += w0 * a; acc[1] += w1 * a; acc[2] += w2 * a;
            acc[3] += w0 * b; acc[4] += w1 * b; acc[5] += w2 * b;
        }
        int v = tid;
        for (; v + NTHR < nvec; v += 2 * NTHR) {
            int d0 = hc + (v << 2), d1 = d0 + (NTHR << 2);
            float4 a0 = ldw(wr + d0), b0 = ldw(wz + d0), e0 = ldw(wn + d0);
            float4 a1 = ldw(wr + d1), b1 = ldw(wz + d1), e1 = ldw(wn + d1);
            float4 p0 = ldx(x1c + d0), q0 = ldx(x2c + d0);
            float4 p1 = ldx(x1c + d1), q1 = ldx(x2c + d1);
            acc[0] += dot4(a0, p0); acc[1] += dot4(b0, p0); acc[2] += dot4(e0, p0);
            acc[3] += dot4(a0, q0); acc[4] += dot4(b0, q0); acc[5] += dot4(e0, q0);
            acc[0] += dot4(a1, p1); acc[1] += dot4(b1, p1); acc[2] += dot4(e1, p1);
            acc[3] += dot4(a1, q1); acc[4] += dot4(b1, q1); acc[5] += dot4(e1, q1);
        }
        for (; v < nvec; v += NTHR) {
            int d0 = hc + (v << 2);
            float4 a0 = ldw(wr + d0), b0 = ldw(wz + d0), e0 = ldw(wn + d0);
            float4 p0 = ldx(x1c + d0), q0 = ldx(x2c + d0);
            acc[0] += dot4(a0, p0); acc[1] += dot4(b0, p0); acc[2] += dot4(e0, p0);
            acc[3] += dot4(a0, q0); acc[4] += dot4(b0, q0); acc[5] += dot4(e0, q0);
        }
        if (tid < tail) {
            int d = hc + (nvec << 2) + tid;
            float a = x1c[d], b = x2c[d];
            float w0 = wr[d], w1 = wz[d], w2 = wn[d];
            acc[0] += w0 * a; acc[1] += w1 * a; acc[2] += w2 * a;
            acc[3] += w0 * b; acc[4] += w1 * b; acc[5] += w2 * b;
        }

        // hidden-hidden part: H = OSC = 2048 -> exactly 2 vec cols per thread
        {
            const float* ur = whh + (size_t)j * OSC;
            const float* uz = ur + (size_t)OSC * OSC;
            const float* un = uz + (size_t)OSC * OSC;
            int d0 = tid << 2, d1 = d0 + 1024;
            float4 u0 = ldw(ur + d0), u1 = ldw(uz + d0), u2 = ldw(un + d0);
            float4 u3 = ldw(ur + d1), u4 = ldw(uz + d1), u5 = ldw(un + d1);
            float4 p0 = ldx(h1g + d0), p1 = ldx(h1g + d1);
            float4 q0 = ldx(h2g + d0), q1 = ldx(h2g + d1);
            acc[6]  += dot4(u0, p0) + dot4(u3, p1);
            acc[7]  += dot4(u1, p0) + dot4(u4, p1);
            acc[8]  += dot4(u2, p0) + dot4(u5, p1);
            acc[9]  += dot4(u0, q0) + dot4(u3, q1);
            acc[10] += dot4(u1, q0) + dot4(u4, q1);
            acc[11] += dot4(u2, q0) + dot4(u5, q1);
        }

        float s[12];
        blockReduce<12>(acc, s);
        if (tid == 0) {
            float br = bih[j], bz = bih[OSC + j], bn = bih[2 * OSC + j];
            float cr = bhh[j], cz = bhh[OSC + j], cn = bhh[2 * OSC + j];
            {
                float r = sigm(s[0] + br + s[6] + cr);
                float z = sigm(s[1] + bz + s[7] + cz);
                float n = tanhf(s[2] + bn + r * (s[8] + cn));
                out1[j] = (1.0f - z) * n + z * h1g[j];
            }
            {
                float r = sigm(s[3] + br + s[9] + cr);
                float z = sigm(s[4] + bz + s[10] + cz);
                float n = tanhf(s[5] + bn + r * (s[11] + cn));
                out2[j] = (1.0f - z) * n + z * h2g[j];
            }
        }
        __syncthreads();   // protect reduce smem before next unit
    }
    if (tid == 0) signal(&g_cnt_done);
}

// ---------------- K0: prep ----------------
__global__ __launch_bounds__(NTHR) void k_prep(
    const float* __restrict__ x,
    const float* __restrict__ h1s, const float* __restrict__ h2s,
    const float* __restrict__ k1s, const float* __restrict__ k2s,
    const float* __restrict__ f1s, const float* __restrict__ f2s)
{
    int i = blockIdx.x * blockDim.x + threadIdx.x;
    if (i == 0) {
#pragma unroll
        for (int h = 0; h < 4; h++) {
            int o = cls_off(h);
            g_xm [h * XM_P + o + 0] = x[0];
            g_xm [h * XM_P + o + 1] = x[1];
            g_xm [h * XM_P + o + 2] = x[8];
            g_xm [h * XM_P + o + 3] = x[9];
            g_xm [h * XM_P + o + 4] = x[10];
            g_xk1[h * XK_P + o] = x[3]; g_xk2[h * XK_P + o] = x[6];
            g_xf1[h * XF_P + o] = x[4]; g_xf2[h * XF_P + o] = x[7];
            g_xh1[h * XH_P + o] = x[2]; g_xh2[h * XH_P + o] = x[5];
        }
        g_cnt_m = 0u; g_cnt_done = 0u;
    }
    if (i < OSC) {
        float h1v = h1s[i], h2v = h2s[i], f1v = f1s[i], f2v = f2s[i];
        float k1v = k1s[i], k2v = k2s[i];
#pragma unroll
        for (int h = 0; h < 4; h++) {
            int o = cls_off(h);
            g_xm [h * XM_P + o + 5 + i]        = h1v;
            g_xm [h * XM_P + o + 5 + OSC + i]  = h2v;
            g_xk1[h * XK_P + o + 1 + i]        = h1v;
            g_xk1[h * XK_P + o + 1 + OSC + i]  = f1v;
            g_xk2[h * XK_P + o + 1 + i]        = h2v;
            g_xk2[h * XK_P + o + 1 + OSC + i]  = f2v;
            g_xf1[h * XF_P + o + 1 + i]        = f1v;
            g_xf2[h * XF_P + o + 1 + i]        = f2v;
            g_xh1[h * XH_P + o + 1 + OSC + i]  = k1v;
            g_xh2[h * XH_P + o + 1 + OSC + i]  = k2v;
        }
    }
}

// ---------------- K_a: m cell (4096) + mout (4096, prefetch+wait) ----------------
__global__ __launch_bounds__(NTHR) void k_a(
    const float* __restrict__ m_s,
    const float* __restrict__ m_wih, const float* __restrict__ m_whh,
    const float* __restrict__ m_bih, const float* __restrict__ m_bhh,
    const float* __restrict__ m_ow,  const float* __restrict__ m_ob)
{
    const int b = blockIdx.x;
    const int tid = threadIdx.x;
    if (b < 4096) {
        gru_unit_single(m_wih, m_whh, m_bih, m_bhh, g_xm, XM_P, 5 + 2 * OSC,
                        m_s, MH, b, g_mnew, &g_cnt_m);
    } else {
        const int r = b - 4096;
        const float* wr = m_ow + (size_t)r * MH;
        int d0 = tid << 2;
        float4 a0 = ldw(wr + d0),        a1 = ldw(wr + d0 + 1024);
        float4 a2 = ldw(wr + d0 + 2048), a3 = ldw(wr + d0 + 3072);
        wait_ge(&g_cnt_m, 4096u);
        float4 m0 = ldcg4(g_mnew + d0),        m1 = ldcg4(g_mnew + d0 + 1024);
        float4 m2 = ldcg4(g_mnew + d0 + 2048), m3 = ldcg4(g_mnew + d0 + 3072);
        float acc[1];
        acc[0] = dot4(a0, m0) + dot4(a1, m1) + dot4(a2, m2) + dot4(a3, m3);
        float s[1];
        blockReduce<1>(acc, s);
        if (tid == 0) {
            float v = s[0] + m_ob[r];
            if (r < OSC) {
#pragma unroll
                for (int h = 0; h < 4; h++) g_xh1[h * XH_P + cls_off(h) + 1 + r] = v;
            } else {
                int rr = r - OSC;
#pragma unroll
                for (int h = 0; h < 4; h++) g_xh2[h * XH_P + cls_off(h) + 1 + rr] = v;
            }
        }
    }
}

// ---------------- K_b: k(512) + f(512) + h(512) batched + 6 heads ----------------
__global__ __launch_bounds__(NTHR) void k_b(
    const float* __restrict__ h1s, const float* __restrict__ h2s,
    const float* __restrict__ k1s, const float* __restrict__ k2s,
    const float* __restrict__ f1s, const float* __restrict__ f2s,
    const float* __restrict__ h_wih, const float* __restrict__ h_whh,
    const float* __restrict__ h_bih, const float* __restrict__ h_bhh,
    const float* __restrict__ h_ow,  const float* __restrict__ h_ob,
    const float* __restrict__ k_wih, const float* __restrict__ k_whh,
    const float* __restrict__ k_bih, const float* __restrict__ k_bhh,
    const float* __restrict__ k_ow,  const float* __restrict__ k_ob,
    const float* __restrict__ f_wih, const float* __restrict__ f_whh,
    const float* __restrict__ f_bih, const float* __restrict__ f_bhh,
    const float* __restrict__ f_ow,  const float* __restrict__ f_ob,
    float* __restrict__ out)
{
    __shared__ __align__(16) float sx1[XK_P];
    __shared__ __align__(16) float sx2[XK_P];
    const int b = blockIdx.x;
    const int tid = threadIdx.x;

    if (b < 512) {
        dual4(k_wih, k_whh, k_bih, k_bhh, g_xk1, g_xk2, XK_P, 1 + 2 * OSC,
              k1s, k2s, g_k1new, g_k2new, sx1, sx2, b);
    } else if (b < 1024) {
        dual4(f_wih, f_whh, f_bih, f_bhh, g_xf1, g_xf2, XF_P, 1 + OSC,
              f1s, f2s, g_f1new, g_f2new, sx1, sx2, b - 512);
    } else if (b < 1536) {
        dual4(h_wih, h_whh, h_bih, h_bhh, g_xh1, g_xh2, XH_P, 1 + 2 * OSC,
              h1s, h2s, g_h1new, g_h2new, sx1, sx2, b - 1024);
    } else {
        const int hb = b - 1536;
        const float* vec;
        const float* w;
        const float* bp;
        switch (hb) {
            case 0: vec = g_h1new; w = h_ow; bp = h_ob; break;
            case 1: vec = g_k1new; w = k_ow; bp = k_ob; break;
            case 2: vec = g_f1new; w = f_ow; bp = f_ob; break;
            case 3: vec = g_h2new; w = h_ow; bp = h_ob; break;
            case 4: vec = g_k2new; w = k_ow; bp = k_ob; break;
            default: vec = g_f2new; w = f_ow; bp = f_ob; break;
        }
        int d0 = tid << 2;
        float4 a0 = ldx(w + d0), a1 = ldx(w + d0 + 1024);
        wait_ge(&g_cnt_done, 1536u);
        float4 v0 = ldcg4(vec + d0), v1 = ldcg4(vec + d0 + 1024);
        float acc[1];
        acc[0] = dot4(a0, v0) + dot4(a1, v1);
        float s[1];
        blockReduce<1>(acc, s);
        if (tid == 0) out[hb] = s[0] + bp[0];
    }
}

// ---------------- launch ----------------
extern "C" void kernel_launch(void* const* d_in, const int* in_sizes, int n_in,
                              void* d_out, int out_size)
{
    const float* x      = (const float*)d_in[0];
    const float* m_s    = (const float*)d_in[1];
    const float* h1_s   = (const float*)d_in[2];
    const float* h2_s   = (const float*)d_in[3];
    const float* k1_s   = (const float*)d_in[4];
    const float* k2_s   = (const float*)d_in[5];
    const float* f1_s   = (const float*)d_in[6];
    const float* f2_s   = (const float*)d_in[7];
    const float* m_wih  = (const float*)d_in[8];
    const float* m_whh  = (const float*)d_in[9];
    const float* m_bih  = (const float*)d_in[10];
    const float* m_bhh  = (const float*)d_in[11];
    const float* m_ow   = (const float*)d_in[12];
    const float* m_ob   = (const float*)d_in[13];
    const float* h_wih  = (const float*)d_in[14];
    const float* h_whh  = (const float*)d_in[15];
    const float* h_bih  = (const float*)d_in[16];
    const float* h_bhh  = (const float*)d_in[17];
    const float* h_ow   = (const float*)d_in[18];
    const float* h_ob   = (const float*)d_in[19];
    const float* k_wih  = (const float*)d_in[20];
    const float* k_whh  = (const float*)d_in[21];
    const float* k_bih  = (const float*)d_in[22];
    const float* k_bhh  = (const float*)d_in[23];
    const float* k_ow   = (const float*)d_in[24];
    const float* k_ob   = (const float*)d_in[25];
    const float* f_wih  = (const float*)d_in[26];
    const float* f_whh  = (const float*)d_in[27];
    const float* f_bih  = (const float*)d_in[28];
    const float* f_bhh  = (const float*)d_in[29];
    const float* f_ow   = (const float*)d_in[30];
    const float* f_ob   = (const float*)d_in[31];
    float* out = (float*)d_out;

    k_prep<<<(OSC + NTHR - 1) / NTHR, NTHR>>>(x, h1_s, h2_s, k1_s, k2_s, f1_s, f2_s);
    k_a<<<8192, NTHR>>>(m_s, m_wih, m_whh, m_bih, m_bhh, m_ow, m_ob);
    k_b<<<1542, NTHR>>>(h1_s, h2_s, k1_s, k2_s, f1_s, f2_s,
                        h_wih, h_whh, h_bih, h_bhh, h_ow, h_ob,
                        k_wih, k_whh, k_bih, k_bhh, k_ow, k_ob,
                        f_wih, f_whh, f_bih, f_bhh, f_ow, f_ob,
                        out);
}

// round 7
// speedup vs baseline: 1.0802x; 1.0802x over previous
#include <cuda_runtime.h>

#define OSC 2048
#define MH  4096
#define NTHR 256

#define XM_P  4104
#define XK_P  4100
#define XF_P  2052
#define SH_P  2052   // shifted 2048-vectors (k-state, out_m halves)

// ---------------- scratch (no allocs allowed) ----------------
__device__ __align__(16) float g_xm [4 * XM_P];
__device__ __align__(16) float g_xk1[4 * XK_P], g_xk2[4 * XK_P];
__device__ __align__(16) float g_xf1[4 * XF_P], g_xf2[4 * XF_P];
__device__ __align__(16) float g_sk1[4 * SH_P], g_sk2[4 * SH_P];  // k1_s/k2_s shifted
__device__ __align__(16) float g_so1[4 * SH_P], g_so2[4 * SH_P];  // out_m halves shifted
__device__ __align__(16) float g_mnew[MH];
__device__ __align__(16) float g_h1new[OSC], g_h2new[OSC];
__device__ __align__(16) float g_k1new[OSC], g_k2new[OSC];
__device__ __align__(16) float g_f1new[OSC], g_f2new[OSC];
__device__ __align__(16) float g_hp[OSC][12];  // h partials: [gi1(3), gi2(3), gh1(3), gh2(3)]
__device__ float g_hx[2];                       // x[2], x[5]

__device__ __forceinline__ float sigm(float v) { return 1.0f / (1.0f + __expf(-v)); }
__device__ __forceinline__ int cls_off(int h) { return (4 - h) & 3; }

__device__ __forceinline__ float4 ldw(const float* p) {
    return __ldcs(reinterpret_cast<const float4*>(p));
}
__device__ __forceinline__ float4 ldx(const float* p) {
    return *reinterpret_cast<const float4*>(p);
}
__device__ __forceinline__ float dot4(float4 a, float4 b) {
    return a.x * b.x + a.y * b.y + a.z * b.z + a.w * b.w;
}

template <int NS>
__device__ __forceinline__ void blockReduce(float (&acc)[NS], float (&out)[NS]) {
    __shared__ float sm[NS][NTHR / 32];
    const int lane = threadIdx.x & 31;
    const int wid  = threadIdx.x >> 5;
#pragma unroll
    for (int s = 0; s < NS; s++) {
        float v = acc[s];
        v += __shfl_down_sync(0xffffffffu, v, 16);
        v += __shfl_down_sync(0xffffffffu, v, 8);
        v += __shfl_down_sync(0xffffffffu, v, 4);
        v += __shfl_down_sync(0xffffffffu, v, 2);
        v += __shfl_down_sync(0xffffffffu, v, 1);
        if (lane == 0) sm[s][wid] = v;
    }
    __syncthreads();
    if (threadIdx.x == 0) {
#pragma unroll
        for (int s = 0; s < NS; s++) {
            float v = 0.0f;
#pragma unroll
            for (int w = 0; w < NTHR / 32; w++) v += sm[s][w];
            out[s] = v;
        }
    }
}

// -------- single-stream GRU unit (m cell) --------
__device__ __forceinline__ void gru_unit_single(
    const float* __restrict__ wih, const float* __restrict__ whh,
    const float* __restrict__ bih, const float* __restrict__ bhh,
    const float* __restrict__ xbufs, int pad, int D,
    const float* __restrict__ hprev, int H, int j,
    float* __restrict__ newout)
{
    float acc[6] = {0, 0, 0, 0, 0, 0};
    const int head = (4 - (j & 3)) & 3;
    const float* xc = xbufs + head * pad + cls_off(head);
    const float* wr = wih + (size_t)j * D;
    const float* wz = wih + (size_t)(H + j) * D;
    const float* wn = wih + (size_t)(2 * H + j) * D;
    const int nvec = (D - head) >> 2;
    const int tail = D - head - (nvec << 2);

    if (threadIdx.x < (unsigned)head) {
        int d = threadIdx.x;
        float xv = xc[d];
        acc[0] += wr[d] * xv; acc[1] += wz[d] * xv; acc[2] += wn[d] * xv;
    }
    int c = threadIdx.x;
    for (; c + NTHR < nvec; c += 2 * NTHR) {
        int d0 = head + (c << 2);
        int d1 = d0 + (NTHR << 2);
        float4 a0 = ldw(wr + d0), b0 = ldw(wz + d0), e0 = ldw(wn + d0);
        float4 a1 = ldw(wr + d1), b1 = ldw(wz + d1), e1 = ldw(wn + d1);
        float4 x0 = ldx(xc + d0), x1 = ldx(xc + d1);
        acc[0] += dot4(a0, x0); acc[1] += dot4(b0, x0); acc[2] += dot4(e0, x0);
        acc[0] += dot4(a1, x1); acc[1] += dot4(b1, x1); acc[2] += dot4(e1, x1);
    }
    if (c < nvec) {
        int d0 = head + (c << 2);
        float4 a0 = ldw(wr + d0), b0 = ldw(wz + d0), e0 = ldw(wn + d0);
        float4 x0 = ldx(xc + d0);
        acc[0] += dot4(a0, x0); acc[1] += dot4(b0, x0); acc[2] += dot4(e0, x0);
    }
    if (threadIdx.x < (unsigned)tail) {
        int d = head + (nvec << 2) + threadIdx.x;
        float xv = xc[d];
        acc[0] += wr[d] * xv; acc[1] += wz[d] * xv; acc[2] += wn[d] * xv;
    }

    const float* ur = whh + (size_t)j * H;
    const float* uz = whh + (size_t)(H + j) * H;
    const float* un = whh + (size_t)(2 * H + j) * H;
    const int nvh = H >> 2;
    c = threadIdx.x;
    for (; c + NTHR < nvh; c += 2 * NTHR) {
        int d0 = c << 2, d1 = d0 + (NTHR << 2);
        float4 a0 = ldw(ur + d0), b0 = ldw(uz + d0), e0 = ldw(un + d0);
        float4 a1 = ldw(ur + d1), b1 = ldw(uz + d1), e1 = ldw(un + d1);
        float4 h0 = ldx(hprev + d0), h1v = ldx(hprev + d1);
        acc[3] += dot4(a0, h0); acc[4] += dot4(b0, h0); acc[5] += dot4(e0, h0);
        acc[3] += dot4(a1, h1v); acc[4] += dot4(b1, h1v); acc[5] += dot4(e1, h1v);
    }
    if (c < nvh) {
        int d0 = c << 2;
        float4 a0 = ldw(ur + d0), b0 = ldw(uz + d0), e0 = ldw(un + d0);
        float4 h0 = ldx(hprev + d0);
        acc[3] += dot4(a0, h0); acc[4] += dot4(b0, h0); acc[5] += dot4(e0, h0);
    }

    float s[6];
    blockReduce<6>(acc, s);
    if (threadIdx.x == 0) {
        float r = sigm(s[0] + bih[j] + s[3] + bhh[j]);
        float z = sigm(s[1] + bih[H + j] + s[4] + bhh[H + j]);
        float n = tanhf(s[2] + bih[2 * H + j] + r * (s[5] + bhh[2 * H + j]));
        newout[j] = (1.0f - z) * n + z * hprev[j];
    }
}

// -------- dual-stream GRU unit (k/f cells) --------
__device__ __forceinline__ void gru_unit_dual(
    const float* __restrict__ wih, const float* __restrict__ whh,
    const float* __restrict__ bih, const float* __restrict__ bhh,
    const float* __restrict__ x1bufs, const float* __restrict__ x2bufs, int pad, int D,
    const float* __restrict__ h1, const float* __restrict__ h2, int H, int j,
    float* __restrict__ out1, float* __restrict__ out2)
{
    float acc[12] = {0, 0, 0, 0, 0, 0, 0, 0, 0, 0, 0, 0};
    const int head = (4 - (j & 3)) & 3;
    const int off  = head * pad + cls_off(head);
    const float* x1c = x1bufs + off;
    const float* x2c = x2bufs + off;
    const float* wr = wih + (size_t)j * D;
    const float* wz = wih + (size_t)(H + j) * D;
    const float* wn = wih + (size_t)(2 * H + j) * D;
    const int nvec = (D - head) >> 2;
    const int tail = D - head - (nvec << 2);

    if (threadIdx.x < (unsigned)head) {
        int d = threadIdx.x;
        float a = x1c[d], b = x2c[d];
        float w0 = wr[d], w1 = wz[d], w2 = wn[d];
        acc[0] += w0 * a; acc[1] += w1 * a; acc[2] += w2 * a;
        acc[3] += w0 * b; acc[4] += w1 * b; acc[5] += w2 * b;
    }
    int c = threadIdx.x;
    for (; c + NTHR < nvec; c += 2 * NTHR) {
        int d0 = head + (c << 2), d1 = d0 + (NTHR << 2);
        float4 a0 = ldw(wr + d0), b0 = ldw(wz + d0), e0 = ldw(wn + d0);
        float4 a1 = ldw(wr + d1), b1 = ldw(wz + d1), e1 = ldw(wn + d1);
        float4 p0 = ldx(x1c + d0), q0 = ldx(x2c + d0);
        float4 p1 = ldx(x1c + d1), q1 = ldx(x2c + d1);
        acc[0] += dot4(a0, p0); acc[1] += dot4(b0, p0); acc[2] += dot4(e0, p0);
        acc[3] += dot4(a0, q0); acc[4] += dot4(b0, q0); acc[5] += dot4(e0, q0);
        acc[0] += dot4(a1, p1); acc[1] += dot4(b1, p1); acc[2] += dot4(e1, p1);
        acc[3] += dot4(a1, q1); acc[4] += dot4(b1, q1); acc[5] += dot4(e1, q1);
    }
    if (c < nvec) {
        int d0 = head + (c << 2);
        float4 a0 = ldw(wr + d0), b0 = ldw(wz + d0), e0 = ldw(wn + d0);
        float4 p0 = ldx(x1c + d0), q0 = ldx(x2c + d0);
        acc[0] += dot4(a0, p0); acc[1] += dot4(b0, p0); acc[2] += dot4(e0, p0);
        acc[3] += dot4(a0, q0); acc[4] += dot4(b0, q0); acc[5] += dot4(e0, q0);
    }
    if (threadIdx.x < (unsigned)tail) {
        int d = head + (nvec << 2) + threadIdx.x;
        float a = x1c[d], b = x2c[d];
        float w0 = wr[d], w1 = wz[d], w2 = wn[d];
        acc[0] += w0 * a; acc[1] += w1 * a; acc[2] += w2 * a;
        acc[3] += w0 * b; acc[4] += w1 * b; acc[5] += w2 * b;
    }

    const float* ur = whh + (size_t)j * H;
    const float* uz = whh + (size_t)(H + j) * H;
    const float* un = whh + (size_t)(2 * H + j) * H;
    const int nvh = H >> 2;
    c = threadIdx.x;
    for (; c + NTHR < nvh; c += 2 * NTHR) {
        int d0 = c << 2, d1 = d0 + (NTHR << 2);
        float4 a0 = ldw(ur + d0), b0 = ldw(uz + d0), e0 = ldw(un + d0);
        float4 a1 = ldw(ur + d1), b1 = ldw(uz + d1), e1 = ldw(un + d1);
        float4 p0 = ldx(h1 + d0), q0 = ldx(h2 + d0);
        float4 p1 = ldx(h1 + d1), q1 = ldx(h2 + d1);
        acc[6] += dot4(a0, p0); acc[7]  += dot4(b0, p0); acc[8]  += dot4(e0, p0);
        acc[9] += dot4(a0, q0); acc[10] += dot4(b0, q0); acc[11] += dot4(e0, q0);
        acc[6] += dot4(a1, p1); acc[7]  += dot4(b1, p1); acc[8]  += dot4(e1, p1);
        acc[9] += dot4(a1, q1); acc[10] += dot4(b1, q1); acc[11] += dot4(e1, q1);
    }
    if (c < nvh) {
        int d0 = c << 2;
        float4 a0 = ldw(ur + d0), b0 = ldw(uz + d0), e0 = ldw(un + d0);
        float4 p0 = ldx(h1 + d0), q0 = ldx(h2 + d0);
        acc[6] += dot4(a0, p0); acc[7]  += dot4(b0, p0); acc[8]  += dot4(e0, p0);
        acc[9] += dot4(a0, q0); acc[10] += dot4(b0, q0); acc[11] += dot4(e0, q0);
    }

    float s[12];
    blockReduce<12>(acc, s);
    if (threadIdx.x == 0) {
        float br = bih[j], bz = bih[H + j], bn = bih[2 * H + j];
        float cr = bhh[j], cz = bhh[H + j], cn = bhh[2 * H + j];
        {
            float r = sigm(s[0] + br + s[6] + cr);
            float z = sigm(s[1] + bz + s[7] + cz);
            float n = tanhf(s[2] + bn + r * (s[8] + cn));
            out1[j] = (1.0f - z) * n + z * h1[j];
        }
        {
            float r = sigm(s[3] + br + s[9] + cr);
            float z = sigm(s[4] + bz + s[10] + cz);
            float n = tanhf(s[5] + bn + r * (s[11] + cn));
            out2[j] = (1.0f - z) * n + z * h2[j];
        }
    }
}

// ---------------- K0: prep, one (copy,i) pair per thread ----------------
__global__ __launch_bounds__(NTHR) void k_prep(
    const float* __restrict__ x,
    const float* __restrict__ h1s, const float* __restrict__ h2s,
    const float* __restrict__ k1s, const float* __restrict__ k2s,
    const float* __restrict__ f1s, const float* __restrict__ f2s)
{
    int idx = blockIdx.x * blockDim.x + threadIdx.x;   // [0, 4*OSC)
    int h = idx >> 11;
    int i = idx & (OSC - 1);
    if (idx == 0) {
#pragma unroll
        for (int c = 0; c < 4; c++) {
            int o = cls_off(c);
            g_xm [c * XM_P + o + 0] = x[0];
            g_xm [c * XM_P + o + 1] = x[1];
            g_xm [c * XM_P + o + 2] = x[8];
            g_xm [c * XM_P + o + 3] = x[9];
            g_xm [c * XM_P + o + 4] = x[10];
            g_xk1[c * XK_P + o] = x[3]; g_xk2[c * XK_P + o] = x[6];
            g_xf1[c * XF_P + o] = x[4]; g_xf2[c * XF_P + o] = x[7];
        }
        g_hx[0] = x[2];
        g_hx[1] = x[5];
    }
    {
        float h1v = h1s[i], h2v = h2s[i], f1v = f1s[i], f2v = f2s[i];
        float k1v = k1s[i], k2v = k2s[i];
        int o = cls_off(h);
        g_xm [h * XM_P + o + 5 + i]        = h1v;
        g_xm [h * XM_P + o + 5 + OSC + i]  = h2v;
        g_xk1[h * XK_P + o + 1 + i]        = h1v;
        g_xk1[h * XK_P + o + 1 + OSC + i]  = f1v;
        g_xk2[h * XK_P + o + 1 + i]        = h2v;
        g_xk2[h * XK_P + o + 1 + OSC + i]  = f2v;
        g_xf1[h * XF_P + o + 1 + i]        = f1v;
        g_xf2[h * XF_P + o + 1 + i]        = f2v;
        g_sk1[h * SH_P + h + i] = k1v;
        g_sk2[h * SH_P + h + i] = k2v;
    }
}

// ---------------- K1: m + k + f + h_ind (all input-only; no sync) ----------------
// blocks: [0,4096) m | [4096,6144) k | [6144,8192) f | [8192,10240) h_ind
__global__ __launch_bounds__(NTHR) void k_main(
    const float* __restrict__ m_s,
    const float* __restrict__ h1s, const float* __restrict__ h2s,
    const float* __restrict__ k1s, const float* __restrict__ k2s,
    const float* __restrict__ f1s, const float* __restrict__ f2s,
    const float* __restrict__ m_wih, const float* __restrict__ m_whh,
    const float* __restrict__ m_bih, const float* __restrict__ m_bhh,
    const float* __restrict__ h_wih, const float* __restrict__ h_whh,
    const float* __restrict__ k_wih, const float* __restrict__ k_whh,
    const float* __restrict__ k_bih, const float* __restrict__ k_bhh,
    const float* __restrict__ f_wih, const float* __restrict__ f_whh,
    const float* __restrict__ f_bih, const float* __restrict__ f_bhh)
{
    const int b = blockIdx.x;
    const int tid = threadIdx.x;

    if (b < 4096) {
        gru_unit_single(m_wih, m_whh, m_bih, m_bhh, g_xm, XM_P, 5 + 2 * OSC,
                        m_s, MH, b, g_mnew);
    } else if (b < 6144) {
        gru_unit_dual(k_wih, k_whh, k_bih, k_bhh, g_xk1, g_xk2, XK_P, 1 + 2 * OSC,
                      k1s, k2s, OSC, b - 4096, g_k1new, g_k2new);
    } else if (b < 8192) {
        gru_unit_dual(f_wih, f_whh, f_bih, f_bhh, g_xf1, g_xf2, XF_P, 1 + OSC,
                      f1s, f2s, OSC, b - 6144, g_f1new, g_f2new);
    } else {
        // ---- h_ind: whh + wih col0 + wih cols [2049,4097) -> partials ----
        const int j = b - 8192;
        const int a = (j + 1) & 3;
        const int head = (4 - a) & 3;
        float acc[12] = {0,0,0,0,0,0,0,0,0,0,0,0};

        // whh (aligned): 512 vec cols, 2 per thread
        {
            const float* ur = h_whh + (size_t)j * OSC;
            const float* uz = ur + (size_t)OSC * OSC;
            const float* un = uz + (size_t)OSC * OSC;
            int d0 = tid << 2, d1 = d0 + 1024;
            float4 u0 = ldw(ur + d0), u1 = ldw(uz + d0), u2 = ldw(un + d0);
            float4 u3 = ldw(ur + d1), u4 = ldw(uz + d1), u5 = ldw(un + d1);
            float4 p0 = ldx(h1s + d0), p1 = ldx(h1s + d1);
            float4 q0 = ldx(h2s + d0), q1 = ldx(h2s + d1);
            acc[6] = dot4(u0, p0) + dot4(u3, p1);
            acc[7] = dot4(u1, p0) + dot4(u4, p1);
            acc[8] = dot4(u2, p0) + dot4(u5, p1);
            acc[9]  = dot4(u0, q0) + dot4(u3, q1);
            acc[10] = dot4(u1, q0) + dot4(u4, q1);
            acc[11] = dot4(u2, q0) + dot4(u5, q1);
        }
        // wih independent segment [2049, 4097): x = k1_s/k2_s
        {
            const float* wr = h_wih + (size_t)j * 4097 + 2049;
            const float* wz = wr + (size_t)OSC * 4097;
            const float* wn = wz + (size_t)OSC * 4097;
            const float* xk1 = g_sk1 + a * SH_P + a;
            const float* xk2 = g_sk2 + a * SH_P + a;
            const int nv = (2048 - head) >> 2;
            int e0 = head + (tid << 2);
            float4 w0 = ldw(wr + e0), w1 = ldw(wz + e0), w2 = ldw(wn + e0);
            float4 xp = ldx(xk1 + e0), xq = ldx(xk2 + e0);
            acc[0] += dot4(w0, xp); acc[1] += dot4(w1, xp); acc[2] += dot4(w2, xp);
            acc[3] += dot4(w0, xq); acc[4] += dot4(w1, xq); acc[5] += dot4(w2, xq);
            if (tid + NTHR < nv) {
                int e1 = head + ((tid + NTHR) << 2);
                float4 w3 = ldw(wr + e1), w4 = ldw(wz + e1), w5 = ldw(wn + e1);
                float4 xp1 = ldx(xk1 + e1), xq1 = ldx(xk2 + e1);
                acc[0] += dot4(w3, xp1); acc[1] += dot4(w4, xp1); acc[2] += dot4(w5, xp1);
                acc[3] += dot4(w3, xq1); acc[4] += dot4(w4, xq1); acc[5] += dot4(w5, xq1);
            }
            if (tid < head) {
                float xa = xk1[tid], xb = xk2[tid];
                float s0 = wr[tid], s1 = wz[tid], s2 = wn[tid];
                acc[0] += s0 * xa; acc[1] += s1 * xa; acc[2] += s2 * xa;
                acc[3] += s0 * xb; acc[4] += s1 * xb; acc[5] += s2 * xb;
            }
            const int tstart = head + (nv << 2);
            const int tcount = 2048 - tstart;
            if (tid >= 32 && tid - 32 < tcount) {
                int t = tstart + (tid - 32);
                float xa = xk1[t], xb = xk2[t];
                float s0 = wr[t], s1 = wz[t], s2 = wn[t];
                acc[0] += s0 * xa; acc[1] += s1 * xa; acc[2] += s2 * xa;
                acc[3] += s0 * xb; acc[4] += s1 * xb; acc[5] += s2 * xb;
            }
            if (tid == 64) {
                // wih col 0 (x = h observation scalars)
                const float* w0p = h_wih + (size_t)j * 4097;
                float w0 = w0p[0];
                float w1 = w0p[(size_t)OSC * 4097];
                float w2 = w0p[(size_t)2 * OSC * 4097];
                float hx1 = g_hx[0], hx2 = g_hx[1];
                acc[0] += w0 * hx1; acc[1] += w1 * hx1; acc[2] += w2 * hx1;
                acc[3] += w0 * hx2; acc[4] += w1 * hx2; acc[5] += w2 * hx2;
            }
        }
        float s[12];
        blockReduce<12>(acc, s);
        if (tid == 0) {
#pragma unroll
            for (int i = 0; i < 12; i++) g_hp[j][i] = s[i];
        }
    }
}

// ---------------- K2: mout (straight-line 8-load body) ----------------
__global__ __launch_bounds__(NTHR) void k_mout(
    const float* __restrict__ w, const float* __restrict__ bias)
{
    int r = blockIdx.x;
    const float* wr = w + (size_t)r * MH;
    int d0 = threadIdx.x << 2;
    float4 a0 = ldw(wr + d0),        a1 = ldw(wr + d0 + 1024);
    float4 a2 = ldw(wr + d0 + 2048), a3 = ldw(wr + d0 + 3072);
    float4 m0 = ldx(g_mnew + d0),        m1 = ldx(g_mnew + d0 + 1024);
    float4 m2 = ldx(g_mnew + d0 + 2048), m3 = ldx(g_mnew + d0 + 3072);
    float acc[1];
    acc[0] = dot4(a0, m0) + dot4(a1, m1) + dot4(a2, m2) + dot4(a3, m3);
    float s[1];
    blockReduce<1>(acc, s);
    if (threadIdx.x == 0) {
        float v = s[0] + bias[r];
        if (r < OSC) {
#pragma unroll
            for (int o = 0; o < 4; o++) g_so1[o * SH_P + o + r] = v;
        } else {
            int rr = r - OSC;
#pragma unroll
            for (int o = 0; o < 4; o++) g_so2[o * SH_P + o + rr] = v;
        }
    }
}

// ---------------- K3: h_dep — wih cols [1,2049) + finish gates ----------------
__global__ __launch_bounds__(NTHR) void k_hdep(
    const float* __restrict__ h_wih,
    const float* __restrict__ h_bih, const float* __restrict__ h_bhh,
    const float* __restrict__ h1s, const float* __restrict__ h2s)
{
    const int j = blockIdx.x;
    const int tid = threadIdx.x;
    const int a = (j + 1) & 3;
    const int head = (4 - a) & 3;
    const int nv = (2048 - head) >> 2;
    const float* wr = h_wih + (size_t)j * 4097 + 1;
    const float* wz = wr + (size_t)OSC * 4097;
    const float* wn = wz + (size_t)OSC * 4097;
    const float* xo1 = g_so1 + a * SH_P + a;
    const float* xo2 = g_so2 + a * SH_P + a;

    float acc[6] = {0, 0, 0, 0, 0, 0};
    int e0 = head + (tid << 2);
    float4 w0 = ldw(wr + e0), w1 = ldw(wz + e0), w2 = ldw(wn + e0);
    float4 p0 = ldx(xo1 + e0), q0 = ldx(xo2 + e0);
    acc[0] += dot4(w0, p0); acc[1] += dot4(w1, p0); acc[2] += dot4(w2, p0);
    acc[3] += dot4(w0, q0); acc[4] += dot4(w1, q0); acc[5] += dot4(w2, q0);
    if (tid + NTHR < nv) {
        int e1 = head + ((tid + NTHR) << 2);
        float4 w3 = ldw(wr + e1), w4 = ldw(wz + e1), w5 = ldw(wn + e1);
        float4 p1 = ldx(xo1 + e1), q1 = ldx(xo2 + e1);
        acc[0] += dot4(w3, p1); acc[1] += dot4(w4, p1); acc[2] += dot4(w5, p1);
        acc[3] += dot4(w3, q1); acc[4] += dot4(w4, q1); acc[5] += dot4(w5, q1);
    }
    if (tid < head) {
        float xa = xo1[tid], xb = xo2[tid];
        float s0 = wr[tid], s1 = wz[tid], s2 = wn[tid];
        acc[0] += s0 * xa; acc[1] += s1 * xa; acc[2] += s2 * xa;
        acc[3] += s0 * xb; acc[4] += s1 * xb; acc[5] += s2 * xb;
    }
    const int tstart = head + (nv << 2);
    const int tcount = 2048 - tstart;
    if (tid >= 32 && tid - 32 < tcount) {
        int t = tstart + (tid - 32);
        float xa = xo1[t], xb = xo2[t];
        float s0 = wr[t], s1 = wz[t], s2 = wn[t];
        acc[0] += s0 * xa; acc[1] += s1 * xa; acc[2] += s2 * xa;
        acc[3] += s0 * xb; acc[4] += s1 * xb; acc[5] += s2 * xb;
    }

    float s[6];
    blockReduce<6>(acc, s);
    if (tid == 0) {
        float p[12];
#pragma unroll
        for (int i = 0; i < 12; i++) p[i] = g_hp[j][i];
        float br = h_bih[j], bz = h_bih[OSC + j], bn = h_bih[2 * OSC + j];
        float cr = h_bhh[j], cz = h_bhh[OSC + j], cn = h_bhh[2 * OSC + j];
        {
            float r = sigm(p[0] + s[0] + br + p[6] + cr);
            float z = sigm(p[1] + s[1] + bz + p[7] + cz);
            float n = tanhf(p[2] + s[2] + bn + r * (p[8] + cn));
            g_h1new[j] = (1.0f - z) * n + z * h1s[j];
        }
        {
            float r = sigm(p[3] + s[3] + br + p[9] + cr);
            float z = sigm(p[4] + s[4] + bz + p[10] + cz);
            float n = tanhf(p[5] + s[5] + bn + r * (p[11] + cn));
            g_h2new[j] = (1.0f - z) * n + z * h2s[j];
        }
    }
}

// ---------------- K4: six output dot products ----------------
__global__ __launch_bounds__(NTHR) void k_heads(
    const float* __restrict__ h_ow, const float* __restrict__ h_ob,
    const float* __restrict__ k_ow, const float* __restrict__ k_ob,
    const float* __restrict__ f_ow, const float* __restrict__ f_ob,
    float* __restrict__ out)
{
    int b = blockIdx.x;
    const float* vec;
    const float* w;
    const float* bp;
    switch (b) {
        case 0: vec = g_h1new; w = h_ow; bp = h_ob; break;
        case 1: vec = g_k1new; w = k_ow; bp = k_ob; break;
        case 2: vec = g_f1new; w = f_ow; bp = f_ob; break;
        case 3: vec = g_h2new; w = h_ow; bp = h_ob; break;
        case 4: vec = g_k2new; w = k_ow; bp = k_ob; break;
        default: vec = g_f2new; w = f_ow; bp = f_ob; break;
    }
    int d0 = threadIdx.x << 2;
    float4 a0 = ldx(w + d0), a1 = ldx(w + d0 + 1024);
    float4 v0 = ldx(vec + d0), v1 = ldx(vec + d0 + 1024);
    float acc[1];
    acc[0] = dot4(a0, v0) + dot4(a1, v1);
    float s[1];
    blockReduce<1>(acc, s);
    if (threadIdx.x == 0) out[b] = s[0] + bp[0];
}

// ---------------- launch ----------------
extern "C" void kernel_launch(void* const* d_in, const int* in_sizes, int n_in,
                              void* d_out, int out_size)
{
    const float* x      = (const float*)d_in[0];
    const float* m_s    = (const float*)d_in[1];
    const float* h1_s   = (const float*)d_in[2];
    const float* h2_s   = (const float*)d_in[3];
    const float* k1_s   = (const float*)d_in[4];
    const float* k2_s   = (const float*)d_in[5];
    const float* f1_s   = (const float*)d_in[6];
    const float* f2_s   = (const float*)d_in[7];
    const float* m_wih  = (const float*)d_in[8];
    const float* m_whh  = (const float*)d_in[9];
    const float* m_bih  = (const float*)d_in[10];
    const float* m_bhh  = (const float*)d_in[11];
    const float* m_ow   = (const float*)d_in[12];
    const float* m_ob   = (const float*)d_in[13];
    const float* h_wih  = (const float*)d_in[14];
    const float* h_whh  = (const float*)d_in[15];
    const float* h_bih  = (const float*)d_in[16];
    const float* h_bhh  = (const float*)d_in[17];
    const float* h_ow   = (const float*)d_in[18];
    const float* h_ob   = (const float*)d_in[19];
    const float* k_wih  = (const float*)d_in[20];
    const float* k_whh  = (const float*)d_in[21];
    const float* k_bih  = (const float*)d_in[22];
    const float* k_bhh  = (const float*)d_in[23];
    const float* k_ow   = (const float*)d_in[24];
    const float* k_ob   = (const float*)d_in[25];
    const float* f_wih  = (const float*)d_in[26];
    const float* f_whh  = (const float*)d_in[27];
    const float* f_bih  = (const float*)d_in[28];
    const float* f_bhh  = (const float*)d_in[29];
    const float* f_ow   = (const float*)d_in[30];
    const float* f_ob   = (const float*)d_in[31];
    float* out = (float*)d_out;

    k_prep<<<(4 * OSC) / NTHR, NTHR>>>(x, h1_s, h2_s, k1_s, k2_s, f1_s, f2_s);
    k_main<<<10240, NTHR>>>(m_s, h1_s, h2_s, k1_s, k2_s, f1_s, f2_s,
                            m_wih, m_whh, m_bih, m_bhh,
                            h_wih, h_whh,
                            k_wih, k_whh, k_bih, k_bhh,
                            f_wih, f_whh, f_bih, f_bhh);
    k_mout<<<MH, NTHR>>>(m_ow, m_ob);
    k_hdep<<<OSC, NTHR>>>(h_wih, h_bih, h_bhh, h1_s, h2_s);
    k_heads<<<6, NTHR>>>(h_ow, h_ob, k_ow, k_ob, f_ow, f_ob, out);
}